// round 12
// baseline (speedup 1.0000x reference)
#include <cuda_runtime.h>
#include <cstdint>
#include <math.h>

#define T_TOK 128
#define HID   2048
#define NEXP  64
#define I2    2816
#define INTER 1408
#define TOPK  8
#define NASSIGN 1024

#define KC   32
#define MT   32
#define SBS  36
#define THR  128

#define S1_BLOCKS (NEXP * 11)          // 704 : (e, ib) ib<11, 128 pairs each
#define S2_BLOCKS (NEXP * 8)           // 512 : (e, hb) hb<8, 256 h-rows each
#define CMB_BLOCKS T_TOK               // 128
#define TOTAL_BLOCKS (S1_BLOCKS + S2_BLOCKS + CMB_BLOCKS)   // 1344

#define BUF_FLOATS (256 * SBS + MT * SBS)
#define BUF_BYTES  (BUF_FLOATS * 4)
#define SMEM_BYTES (2 * BUF_BYTES)     // 82944

// ---- scratch ----
__device__ float g_act[NASSIGN * INTER];
__device__ float g_part[NASSIGN * HID];
__device__ float g_gate[NASSIGN];
__device__ int   g_map[NASSIGN];
__device__ int   g_exp[NASSIGN];
__device__ int   g_tok[NASSIGN];
__device__ int   g_off[NEXP + 1];
__device__ int   g_s1done[NEXP];
__device__ int   g_s2cnt[NEXP];

// =====================================================================
// helpers
// =====================================================================
__device__ __forceinline__ unsigned su32(const void* p) {
    return (unsigned)__cvta_generic_to_shared(p);
}
__device__ __forceinline__ void cp16(unsigned dst, const void* src, int bytes) {
    asm volatile("cp.async.cg.shared.global [%0], [%1], 16, %2;\n"
                 :: "r"(dst), "l"(src), "r"(bytes));
}
__device__ __forceinline__ void cp_commit() { asm volatile("cp.async.commit_group;\n"); }
__device__ __forceinline__ void cp_wait0()  { asm volatile("cp.async.wait_group 0;\n"); }

__device__ __forceinline__ unsigned rtf(float f) {   // f32 -> tf32 round-to-nearest
    return __float_as_uint(f) + 0x1000u;
}
__device__ __forceinline__ void mma8(float* d,
                                     unsigned a0, unsigned a1, unsigned a2, unsigned a3,
                                     unsigned b0, unsigned b1) {
    asm volatile(
        "mma.sync.aligned.m16n8k8.row.col.f32.tf32.tf32.f32 "
        "{%0,%1,%2,%3}, {%4,%5,%6,%7}, {%8,%9}, {%0,%1,%2,%3};\n"
        : "+f"(d[0]), "+f"(d[1]), "+f"(d[2]), "+f"(d[3])
        : "r"(a0), "r"(a1), "r"(a2), "r"(a3), "r"(b0), "r"(b1));
}

__device__ __forceinline__ void spin_until(volatile int* p, int need) {
    while (*p < need) __nanosleep(128);
}

// =====================================================================
// Routing (R8 version: shared-atomic count/scatter, order-invariant output)
// =====================================================================
__global__ void routing_kernel(const float* __restrict__ logits) {
    __shared__ float sp[T_TOK][NEXP + 1];
    __shared__ int scnt[NEXP];
    __shared__ int soff[NEXP + 1];
    __shared__ int scur[NEXP];

    const int t = threadIdx.x;   // 128 threads, one token each

    if (t < NEXP) { g_s1done[t] = 0; g_s2cnt[t] = 0; scnt[t] = 0; scur[t] = 0; }
    __syncthreads();

    float mx = -1e30f;
    #pragma unroll 8
    for (int e = 0; e < NEXP; e++) mx = fmaxf(mx, logits[t * NEXP + e]);
    #pragma unroll 8
    for (int e = 0; e < NEXP; e++) sp[t][e] = expf(logits[t * NEXP + e] - mx);

    float wsel[TOPK]; int isel[TOPK];
    for (int s = 0; s < TOPK; s++) {
        float best = -1.f; int bj = 0;
        for (int e = 0; e < NEXP; e++) {
            float v = sp[t][e];
            if (v > best) { best = v; bj = e; }
        }
        wsel[s] = best; isel[s] = bj; sp[t][bj] = -2.f;
    }
    float gs = 0.f;
    #pragma unroll
    for (int s = 0; s < TOPK; s++) gs += wsel[s];
    float inv = 1.f / gs;
    #pragma unroll
    for (int s = 0; s < TOPK; s++) {
        g_gate[t * TOPK + s] = wsel[s] * inv;
        g_exp[t * TOPK + s]  = isel[s];
        atomicAdd(&scnt[isel[s]], 1);
    }
    __syncthreads();

    if (t == 0) {
        int acc = 0;
        for (int e = 0; e < NEXP; e++) { soff[e] = acc; acc += scnt[e]; }
        soff[NEXP] = acc;
        for (int e = 0; e <= NEXP; e++) g_off[e] = soff[e];
    }
    __syncthreads();

    #pragma unroll
    for (int s = 0; s < TOPK; s++) {
        int e = isel[s];
        int pos = soff[e] + atomicAdd(&scur[e], 1);
        g_tok[pos] = t;
        g_map[t * TOPK + s] = pos;
    }
}

// =====================================================================
// Fused MoE kernel (R3 tiles; SINGLE barrier per K-chunk):
//   pipeline: wait0 -> sync -> issue next chunk -> compute
//   buffer safety: by the time any warp issues into buf par^1, all warps
//   passed the sync, i.e. finished compute(kc-1) = last consumer of it.
// bids [0,704) stage1, [704,1216) stage2, [1216,1344) combine
// =====================================================================
__global__ void __launch_bounds__(THR)
moe_kernel(const float* __restrict__ x, const float* __restrict__ w1,
           const float* __restrict__ w2, float* __restrict__ out) {
    extern __shared__ __align__(16) float dynsm[];
    const unsigned smb = su32(dynsm);

    const int bid = blockIdx.x;
    const int tid = threadIdx.x;
    const int wid = tid >> 5, lane = tid & 31;
    const int g   = lane >> 2, tg = lane & 3;
    const int nb  = wid * 64;

    // =========================== STAGE 1 ===========================
    if (bid < S1_BLOCKS) {
        const int e  = bid / 11;
        const int ib = bid % 11;
        const int off = g_off[e];
        const int cnt = g_off[e + 1] - off;
        const int ibase = ib * 128;
        const int ngrp = (cnt + MT - 1) / MT;
        const float* w1e = w1 + (size_t)e * I2 * HID;

        __shared__ int toks[MT];

        const float* bsrc[16];
        unsigned     bdst[16];
        #pragma unroll
        for (int j = 0; j < 16; j++) {
            int idx = j * THR + tid;
            int c = idx >> 3, k4 = idx & 7;
            int p = c >> 1;
            int gr = (c & 1) ? (INTER + ibase + p) : (ibase + p);
            bsrc[j] = w1e + (size_t)gr * HID + k4 * 4;
            bdst[j] = (unsigned)(c * SBS + k4 * 4) * 4u;
        }

        for (int grp = 0; grp < ngrp; grp++) {
            const int m0 = grp * MT;
            if (tid < MT) toks[tid] = (m0 + tid < cnt) ? g_tok[off + m0 + tid] : -1;
            __syncthreads();

            const float* asrc[2];
            int aval[2];
            unsigned adst[2];
            #pragma unroll
            for (int j = 0; j < 2; j++) {
                int idx = j * THR + tid;
                int m = idx >> 3, k4 = idx & 7;
                int tok = toks[m];
                asrc[j] = x + (size_t)(tok < 0 ? 0 : tok) * HID + k4 * 4;
                aval[j] = (tok >= 0) ? 16 : 0;
                adst[j] = (unsigned)((256 * SBS) + m * SBS + k4 * 4) * 4u;
            }

            float acc[2][8][4];
            #pragma unroll
            for (int a = 0; a < 2; a++)
                #pragma unroll
                for (int b = 0; b < 8; b++)
                    #pragma unroll
                    for (int cix = 0; cix < 4; cix++) acc[a][b][cix] = 0.f;

            const int NK = HID / KC;   // 64
            // prologue: chunk 0 -> buffer 0
            #pragma unroll
            for (int j = 0; j < 16; j++) cp16(smb + bdst[j], bsrc[j], 16);
            #pragma unroll
            for (int j = 0; j < 2; j++)  cp16(smb + adst[j], asrc[j], aval[j]);
            cp_commit();

            for (int kc = 0; kc < NK; kc++) {
                const int par = kc & 1;
                cp_wait0();
                __syncthreads();
                if (kc + 1 < NK) {
                    const unsigned boff = (par ^ 1) ? (unsigned)BUF_BYTES : 0u;
                    const int ko = (kc + 1) * KC;
                    #pragma unroll
                    for (int j = 0; j < 16; j++) cp16(smb + boff + bdst[j], bsrc[j] + ko, 16);
                    #pragma unroll
                    for (int j = 0; j < 2; j++)  cp16(smb + boff + adst[j], asrc[j] + ko, aval[j]);
                    cp_commit();
                }

                const float* bB = dynsm + par * BUF_FLOATS;
                const float* bA = bB + 256 * SBS;

                #pragma unroll
                for (int ks = 0; ks < 4; ks++) {
                    unsigned af[2][4];
                    #pragma unroll
                    for (int mt = 0; mt < 2; mt++) {
                        const int r = mt * 16 + g;
                        const float* p0 = bA + r * SBS + ks * 8 + tg;
                        const float* p1 = bA + (r + 8) * SBS + ks * 8 + tg;
                        af[mt][0] = rtf(p0[0]);
                        af[mt][1] = rtf(p1[0]);
                        af[mt][2] = rtf(p0[4]);
                        af[mt][3] = rtf(p1[4]);
                    }
                    #pragma unroll
                    for (int nt = 0; nt < 8; nt++) {
                        const float* pb = bB + (nb + nt * 8 + g) * SBS + ks * 8 + tg;
                        unsigned b0 = rtf(pb[0]);
                        unsigned b1 = rtf(pb[4]);
                        mma8(acc[0][nt], af[0][0], af[0][1], af[0][2], af[0][3], b0, b1);
                        mma8(acc[1][nt], af[1][0], af[1][1], af[1][2], af[1][3], b0, b1);
                    }
                }
            }

            // epilogue: silu(up)*gate, pair interleave keeps both in-thread
            #pragma unroll
            for (int mt = 0; mt < 2; mt++) {
                #pragma unroll
                for (int nt = 0; nt < 8; nt++) {
                    const int pl = ibase + nb / 2 + nt * 4 + tg;
                    const int r0 = mt * 16 + g;
                    const int r1 = r0 + 8;
                    if (m0 + r0 < cnt) {
                        float u = acc[mt][nt][0];
                        g_act[(size_t)(off + m0 + r0) * INTER + pl] =
                            u / (1.f + expf(-u)) * acc[mt][nt][1];
                    }
                    if (m0 + r1 < cnt) {
                        float u = acc[mt][nt][2];
                        g_act[(size_t)(off + m0 + r1) * INTER + pl] =
                            u / (1.f + expf(-u)) * acc[mt][nt][3];
                    }
                }
            }
            __syncthreads();   // group boundary: all compute done before buffers reused
        }

        if (tid == 0) {
            __threadfence();
            atomicAdd(&g_s1done[e], 1);
        }
        return;
    }

    // =========================== STAGE 2 ===========================
    if (bid < S1_BLOCKS + S2_BLOCKS) {
        const int sb = bid - S1_BLOCKS;
        const int e  = sb / 8;
        const int hb = sb % 8;
        const int off = g_off[e];
        const int cnt = g_off[e + 1] - off;
        const int hbase = hb * 256;
        const int ngrp = (cnt + MT - 1) / MT;
        const float* w2e = w2 + (size_t)e * HID * INTER;

        if (tid == 0) {
            spin_until(&g_s1done[e], 11);
            __threadfence();
        }
        __syncthreads();

        const float* bsrc[16];
        unsigned     bdst[16];
        #pragma unroll
        for (int j = 0; j < 16; j++) {
            int idx = j * THR + tid;
            int c = idx >> 3, k4 = idx & 7;
            bsrc[j] = w2e + (size_t)(hbase + c) * INTER + k4 * 4;
            bdst[j] = (unsigned)(c * SBS + k4 * 4) * 4u;
        }

        for (int grp = 0; grp < ngrp; grp++) {
            const int m0 = grp * MT;

            const float* asrc[2];
            int aval[2];
            unsigned adst[2];
            #pragma unroll
            for (int j = 0; j < 2; j++) {
                int idx = j * THR + tid;
                int m = idx >> 3, k4 = idx & 7;
                int valid = (m0 + m) < cnt;
                asrc[j] = g_act + (size_t)(off + (valid ? m0 + m : 0)) * INTER + k4 * 4;
                aval[j] = valid ? 16 : 0;
                adst[j] = (unsigned)((256 * SBS) + m * SBS + k4 * 4) * 4u;
            }

            float acc[2][8][4];
            #pragma unroll
            for (int a = 0; a < 2; a++)
                #pragma unroll
                for (int b = 0; b < 8; b++)
                    #pragma unroll
                    for (int cix = 0; cix < 4; cix++) acc[a][b][cix] = 0.f;

            const int NK = INTER / KC;   // 44
            #pragma unroll
            for (int j = 0; j < 16; j++) cp16(smb + bdst[j], bsrc[j], 16);
            #pragma unroll
            for (int j = 0; j < 2; j++)  cp16(smb + adst[j], asrc[j], aval[j]);
            cp_commit();

            for (int kc = 0; kc < NK; kc++) {
                const int par = kc & 1;
                cp_wait0();
                __syncthreads();
                if (kc + 1 < NK) {
                    const unsigned boff = (par ^ 1) ? (unsigned)BUF_BYTES : 0u;
                    const int ko = (kc + 1) * KC;
                    #pragma unroll
                    for (int j = 0; j < 16; j++) cp16(smb + boff + bdst[j], bsrc[j] + ko, 16);
                    #pragma unroll
                    for (int j = 0; j < 2; j++)  cp16(smb + boff + adst[j], asrc[j] + ko, aval[j]);
                    cp_commit();
                }

                const float* bB = dynsm + par * BUF_FLOATS;
                const float* bA = bB + 256 * SBS;

                #pragma unroll
                for (int ks = 0; ks < 4; ks++) {
                    unsigned af[2][4];
                    #pragma unroll
                    for (int mt = 0; mt < 2; mt++) {
                        const int r = mt * 16 + g;
                        const float* p0 = bA + r * SBS + ks * 8 + tg;
                        const float* p1 = bA + (r + 8) * SBS + ks * 8 + tg;
                        af[mt][0] = rtf(p0[0]);
                        af[mt][1] = rtf(p1[0]);
                        af[mt][2] = rtf(p0[4]);
                        af[mt][3] = rtf(p1[4]);
                    }
                    #pragma unroll
                    for (int nt = 0; nt < 8; nt++) {
                        const float* pb = bB + (nb + nt * 8 + g) * SBS + ks * 8 + tg;
                        unsigned b0 = rtf(pb[0]);
                        unsigned b1 = rtf(pb[4]);
                        mma8(acc[0][nt], af[0][0], af[0][1], af[0][2], af[0][3], b0, b1);
                        mma8(acc[1][nt], af[1][0], af[1][1], af[1][2], af[1][3], b0, b1);
                    }
                }
            }

            #pragma unroll
            for (int mt = 0; mt < 2; mt++) {
                #pragma unroll
                for (int nt = 0; nt < 8; nt++) {
                    const int col = hbase + nb + nt * 8 + 2 * tg;
                    const int r0 = mt * 16 + g;
                    const int r1 = r0 + 8;
                    if (m0 + r0 < cnt) {
                        float2 v = make_float2(acc[mt][nt][0], acc[mt][nt][1]);
                        *(float2*)(g_part + (size_t)(off + m0 + r0) * HID + col) = v;
                    }
                    if (m0 + r1 < cnt) {
                        float2 v = make_float2(acc[mt][nt][2], acc[mt][nt][3]);
                        *(float2*)(g_part + (size_t)(off + m0 + r1) * HID + col) = v;
                    }
                }
            }
            __syncthreads();   // group boundary
        }

        if (tid == 0) {
            __threadfence();
            atomicAdd(&g_s2cnt[e], 1);
        }
        return;
    }

    // =========================== COMBINE ===========================
    {
        const int t = bid - (S1_BLOCKS + S2_BLOCKS);
        // wait only on this token's 8 experts
        if (tid == 0) {
            #pragma unroll
            for (int s = 0; s < TOPK; s++) {
                int es = g_exp[t * TOPK + s];
                spin_until(&g_s2cnt[es], 8);
            }
            __threadfence();
        }
        __syncthreads();

        int   gi[TOPK];
        float gw[TOPK];
        #pragma unroll
        for (int s = 0; s < TOPK; s++) {
            gi[s] = g_map[t * TOPK + s];
            gw[s] = g_gate[t * TOPK + s];
        }
        #pragma unroll
        for (int j = 0; j < 4; j++) {
            const int c4 = tid + j * THR;
            float4 acc = make_float4(0.f, 0.f, 0.f, 0.f);
            #pragma unroll
            for (int s = 0; s < TOPK; s++) {
                const float4 v = *(const float4*)(g_part + (size_t)gi[s] * HID + 4 * c4);
                const float w = gw[s];
                acc.x += w * v.x; acc.y += w * v.y;
                acc.z += w * v.z; acc.w += w * v.w;
            }
            *(float4*)(out + (size_t)t * HID + 4 * c4) = acc;
        }
    }
}

// =====================================================================
extern "C" void kernel_launch(void* const* d_in, const int* in_sizes, int n_in,
                              void* d_out, int out_size) {
    (void)in_sizes; (void)n_in; (void)out_size;
    const float* x      = (const float*)d_in[0];
    const float* logits = (const float*)d_in[1];
    const float* w1     = (const float*)d_in[2];
    const float* w2     = (const float*)d_in[3];
    float* out          = (float*)d_out;

    static int configured = 0;
    if (!configured) {
        cudaFuncSetAttribute(moe_kernel,
                             cudaFuncAttributeMaxDynamicSharedMemorySize, SMEM_BYTES);
        configured = 1;
    }

    routing_kernel<<<1, T_TOK>>>(logits);
    moe_kernel<<<TOTAL_BLOCKS, THR, SMEM_BYTES>>>(x, w1, w2, out);
}

// round 13
// speedup vs baseline: 1.1102x; 1.1102x over previous
#include <cuda_runtime.h>
#include <cstdint>
#include <math.h>

#define T_TOK 128
#define HID   2048
#define NEXP  64
#define I2    2816
#define INTER 1408
#define TOPK  8
#define NASSIGN 1024

#define KC   32
#define MT   32
#define SBS  36
#define THR  128

#define S1_BLOCKS (NEXP * 11)          // 704 : (e, ib) ib<11, 128 pairs each
#define S2_BLOCKS (NEXP * 8)           // 512 : (e, hb) hb<8, 256 h-rows each
#define CMB_BLOCKS T_TOK               // 128
#define TOTAL_BLOCKS (S1_BLOCKS + S2_BLOCKS + CMB_BLOCKS)   // 1344

#define BUF_FLOATS (256 * SBS + MT * SBS)
#define BUF_BYTES  (BUF_FLOATS * 4)
#define SMEM_BYTES (2 * BUF_BYTES)     // 82944

// ---- scratch ----
__device__ float g_act[NASSIGN * INTER];
__device__ float g_part[NASSIGN * HID];
__device__ float g_gate[NASSIGN];
__device__ int   g_map[NASSIGN];
__device__ int   g_exp[NASSIGN];       // (t,slot) -> expert id
__device__ int   g_tok[NASSIGN];
__device__ int   g_off[NEXP + 1];
__device__ int   g_s1done[NEXP];
__device__ int   g_s2cnt[NEXP];

// =====================================================================
// helpers
// =====================================================================
__device__ __forceinline__ unsigned su32(const void* p) {
    return (unsigned)__cvta_generic_to_shared(p);
}
__device__ __forceinline__ void cp16(unsigned dst, const void* src, int bytes) {
    asm volatile("cp.async.cg.shared.global [%0], [%1], 16, %2;\n"
                 :: "r"(dst), "l"(src), "r"(bytes));
}
__device__ __forceinline__ void cp_commit() { asm volatile("cp.async.commit_group;\n"); }
__device__ __forceinline__ void cp_wait1()  { asm volatile("cp.async.wait_group 1;\n"); }
__device__ __forceinline__ void cp_wait0()  { asm volatile("cp.async.wait_group 0;\n"); }

__device__ __forceinline__ unsigned rtf(float f) {   // f32 -> tf32 round-to-nearest
    return __float_as_uint(f) + 0x1000u;
}
__device__ __forceinline__ void mma8(float* d,
                                     unsigned a0, unsigned a1, unsigned a2, unsigned a3,
                                     unsigned b0, unsigned b1) {
    asm volatile(
        "mma.sync.aligned.m16n8k8.row.col.f32.tf32.tf32.f32 "
        "{%0,%1,%2,%3}, {%4,%5,%6,%7}, {%8,%9}, {%0,%1,%2,%3};\n"
        : "+f"(d[0]), "+f"(d[1]), "+f"(d[2]), "+f"(d[3])
        : "r"(a0), "r"(a1), "r"(a2), "r"(a3), "r"(b0), "r"(b1));
}

__device__ __forceinline__ void spin_until(volatile int* p, int need) {
    while (*p < need) __nanosleep(128);
}

// =====================================================================
// Routing: top-8 per token; count/scatter via shared-memory atomics.
// Output bit-identical regardless of scatter order: per-assignment GEMMs
// and fixed-slot-order combine are order-invariant.
// =====================================================================
__global__ void routing_kernel(const float* __restrict__ logits) {
    __shared__ float sp[T_TOK][NEXP + 1];
    __shared__ int scnt[NEXP];
    __shared__ int soff[NEXP + 1];
    __shared__ int scur[NEXP];

    const int t = threadIdx.x;   // 128 threads, one token each

    if (t < NEXP) { g_s1done[t] = 0; g_s2cnt[t] = 0; scnt[t] = 0; scur[t] = 0; }
    __syncthreads();

    float mx = -1e30f;
    #pragma unroll 8
    for (int e = 0; e < NEXP; e++) mx = fmaxf(mx, logits[t * NEXP + e]);
    #pragma unroll 8
    for (int e = 0; e < NEXP; e++) sp[t][e] = expf(logits[t * NEXP + e] - mx);

    float wsel[TOPK]; int isel[TOPK];
    for (int s = 0; s < TOPK; s++) {
        float best = -1.f; int bj = 0;
        for (int e = 0; e < NEXP; e++) {
            float v = sp[t][e];
            if (v > best) { best = v; bj = e; }
        }
        wsel[s] = best; isel[s] = bj; sp[t][bj] = -2.f;
    }
    float gs = 0.f;
    #pragma unroll
    for (int s = 0; s < TOPK; s++) gs += wsel[s];
    float inv = 1.f / gs;
    #pragma unroll
    for (int s = 0; s < TOPK; s++) {
        g_gate[t * TOPK + s] = wsel[s] * inv;
        g_exp[t * TOPK + s]  = isel[s];
        atomicAdd(&scnt[isel[s]], 1);
    }
    __syncthreads();

    if (t == 0) {
        int acc = 0;
        for (int e = 0; e < NEXP; e++) { soff[e] = acc; acc += scnt[e]; }
        soff[NEXP] = acc;
        for (int e = 0; e <= NEXP; e++) g_off[e] = soff[e];
    }
    __syncthreads();

    #pragma unroll
    for (int s = 0; s < TOPK; s++) {
        int e = isel[s];
        int pos = soff[e] + atomicAdd(&scur[e], 1);
        g_tok[pos] = t;
        g_map[t * TOPK + s] = pos;
    }
}

// =====================================================================
// Fused MoE kernel (exact R3 stream; stage2 completion per-expert):
// bids [0,704) stage1, [704,1216) stage2, [1216,1344) combine
// =====================================================================
__global__ void __launch_bounds__(THR)
moe_kernel(const float* __restrict__ x, const float* __restrict__ w1,
           const float* __restrict__ w2, float* __restrict__ out) {
    extern __shared__ __align__(16) float dynsm[];
    const unsigned smb = su32(dynsm);

    const int bid = blockIdx.x;
    const int tid = threadIdx.x;
    const int wid = tid >> 5, lane = tid & 31;
    const int g   = lane >> 2, tg = lane & 3;
    const int nb  = wid * 64;

    // =========================== STAGE 1 ===========================
    if (bid < S1_BLOCKS) {
        const int e  = bid / 11;
        const int ib = bid % 11;
        const int off = g_off[e];
        const int cnt = g_off[e + 1] - off;
        const int ibase = ib * 128;
        const int ngrp = (cnt + MT - 1) / MT;
        const float* w1e = w1 + (size_t)e * I2 * HID;

        __shared__ int toks[MT];

        const float* bsrc[16];
        unsigned     bdst[16];
        #pragma unroll
        for (int j = 0; j < 16; j++) {
            int idx = j * THR + tid;
            int c = idx >> 3, k4 = idx & 7;
            int p = c >> 1;
            int gr = (c & 1) ? (INTER + ibase + p) : (ibase + p);
            bsrc[j] = w1e + (size_t)gr * HID + k4 * 4;
            bdst[j] = (unsigned)(c * SBS + k4 * 4) * 4u;
        }

        for (int grp = 0; grp < ngrp; grp++) {
            const int m0 = grp * MT;
            if (tid < MT) toks[tid] = (m0 + tid < cnt) ? g_tok[off + m0 + tid] : -1;
            __syncthreads();

            const float* asrc[2];
            int aval[2];
            unsigned adst[2];
            #pragma unroll
            for (int j = 0; j < 2; j++) {
                int idx = j * THR + tid;
                int m = idx >> 3, k4 = idx & 7;
                int tok = toks[m];
                asrc[j] = x + (size_t)(tok < 0 ? 0 : tok) * HID + k4 * 4;
                aval[j] = (tok >= 0) ? 16 : 0;
                adst[j] = (unsigned)((256 * SBS) + m * SBS + k4 * 4) * 4u;
            }

            float acc[2][8][4];
            #pragma unroll
            for (int a = 0; a < 2; a++)
                #pragma unroll
                for (int b = 0; b < 8; b++)
                    #pragma unroll
                    for (int cix = 0; cix < 4; cix++) acc[a][b][cix] = 0.f;

            const int NK = HID / KC;   // 64
            #pragma unroll
            for (int j = 0; j < 16; j++) cp16(smb + bdst[j], bsrc[j], 16);
            #pragma unroll
            for (int j = 0; j < 2; j++)  cp16(smb + adst[j], asrc[j], aval[j]);
            cp_commit();

            for (int kc = 0; kc < NK; kc++) {
                const int par = kc & 1;
                if (kc + 1 < NK) {
                    const unsigned boff = (par ^ 1) ? (unsigned)BUF_BYTES : 0u;
                    const int ko = (kc + 1) * KC;
                    #pragma unroll
                    for (int j = 0; j < 16; j++) cp16(smb + boff + bdst[j], bsrc[j] + ko, 16);
                    #pragma unroll
                    for (int j = 0; j < 2; j++)  cp16(smb + boff + adst[j], asrc[j] + ko, aval[j]);
                    cp_commit();
                    cp_wait1();
                } else {
                    cp_wait0();
                }
                __syncthreads();

                const float* bB = dynsm + par * BUF_FLOATS;
                const float* bA = bB + 256 * SBS;

                #pragma unroll
                for (int ks = 0; ks < 4; ks++) {
                    unsigned af[2][4];
                    #pragma unroll
                    for (int mt = 0; mt < 2; mt++) {
                        const int r = mt * 16 + g;
                        const float* p0 = bA + r * SBS + ks * 8 + tg;
                        const float* p1 = bA + (r + 8) * SBS + ks * 8 + tg;
                        af[mt][0] = rtf(p0[0]);
                        af[mt][1] = rtf(p1[0]);
                        af[mt][2] = rtf(p0[4]);
                        af[mt][3] = rtf(p1[4]);
                    }
                    #pragma unroll
                    for (int nt = 0; nt < 8; nt++) {
                        const float* pb = bB + (nb + nt * 8 + g) * SBS + ks * 8 + tg;
                        unsigned b0 = rtf(pb[0]);
                        unsigned b1 = rtf(pb[4]);
                        mma8(acc[0][nt], af[0][0], af[0][1], af[0][2], af[0][3], b0, b1);
                        mma8(acc[1][nt], af[1][0], af[1][1], af[1][2], af[1][3], b0, b1);
                    }
                }
                __syncthreads();
            }

            // epilogue: silu(up)*gate, pair interleave keeps both in-thread
            #pragma unroll
            for (int mt = 0; mt < 2; mt++) {
                #pragma unroll
                for (int nt = 0; nt < 8; nt++) {
                    const int pl = ibase + nb / 2 + nt * 4 + tg;
                    const int r0 = mt * 16 + g;
                    const int r1 = r0 + 8;
                    if (m0 + r0 < cnt) {
                        float u = acc[mt][nt][0];
                        g_act[(size_t)(off + m0 + r0) * INTER + pl] =
                            u / (1.f + expf(-u)) * acc[mt][nt][1];
                    }
                    if (m0 + r1 < cnt) {
                        float u = acc[mt][nt][2];
                        g_act[(size_t)(off + m0 + r1) * INTER + pl] =
                            u / (1.f + expf(-u)) * acc[mt][nt][3];
                    }
                }
            }
            __syncthreads();
        }

        __syncthreads();
        if (tid == 0) {
            __threadfence();
            atomicAdd(&g_s1done[e], 1);
        }
        return;
    }

    // =========================== STAGE 2 ===========================
    if (bid < S1_BLOCKS + S2_BLOCKS) {
        const int sb = bid - S1_BLOCKS;
        const int e  = sb / 8;
        const int hb = sb % 8;
        const int off = g_off[e];
        const int cnt = g_off[e + 1] - off;
        const int hbase = hb * 256;
        const int ngrp = (cnt + MT - 1) / MT;
        const float* w2e = w2 + (size_t)e * HID * INTER;

        if (tid == 0) {
            spin_until(&g_s1done[e], 11);
            __threadfence();
        }
        __syncthreads();

        const float* bsrc[16];
        unsigned     bdst[16];
        #pragma unroll
        for (int j = 0; j < 16; j++) {
            int idx = j * THR + tid;
            int c = idx >> 3, k4 = idx & 7;
            bsrc[j] = w2e + (size_t)(hbase + c) * INTER + k4 * 4;
            bdst[j] = (unsigned)(c * SBS + k4 * 4) * 4u;
        }

        for (int grp = 0; grp < ngrp; grp++) {
            const int m0 = grp * MT;

            const float* asrc[2];
            int aval[2];
            unsigned adst[2];
            #pragma unroll
            for (int j = 0; j < 2; j++) {
                int idx = j * THR + tid;
                int m = idx >> 3, k4 = idx & 7;
                int valid = (m0 + m) < cnt;
                asrc[j] = g_act + (size_t)(off + (valid ? m0 + m : 0)) * INTER + k4 * 4;
                aval[j] = valid ? 16 : 0;
                adst[j] = (unsigned)((256 * SBS) + m * SBS + k4 * 4) * 4u;
            }

            float acc[2][8][4];
            #pragma unroll
            for (int a = 0; a < 2; a++)
                #pragma unroll
                for (int b = 0; b < 8; b++)
                    #pragma unroll
                    for (int cix = 0; cix < 4; cix++) acc[a][b][cix] = 0.f;

            const int NK = INTER / KC;   // 44
            #pragma unroll
            for (int j = 0; j < 16; j++) cp16(smb + bdst[j], bsrc[j], 16);
            #pragma unroll
            for (int j = 0; j < 2; j++)  cp16(smb + adst[j], asrc[j], aval[j]);
            cp_commit();

            for (int kc = 0; kc < NK; kc++) {
                const int par = kc & 1;
                if (kc + 1 < NK) {
                    const unsigned boff = (par ^ 1) ? (unsigned)BUF_BYTES : 0u;
                    const int ko = (kc + 1) * KC;
                    #pragma unroll
                    for (int j = 0; j < 16; j++) cp16(smb + boff + bdst[j], bsrc[j] + ko, 16);
                    #pragma unroll
                    for (int j = 0; j < 2; j++)  cp16(smb + boff + adst[j], asrc[j] + ko, aval[j]);
                    cp_commit();
                    cp_wait1();
                } else {
                    cp_wait0();
                }
                __syncthreads();

                const float* bB = dynsm + par * BUF_FLOATS;
                const float* bA = bB + 256 * SBS;

                #pragma unroll
                for (int ks = 0; ks < 4; ks++) {
                    unsigned af[2][4];
                    #pragma unroll
                    for (int mt = 0; mt < 2; mt++) {
                        const int r = mt * 16 + g;
                        const float* p0 = bA + r * SBS + ks * 8 + tg;
                        const float* p1 = bA + (r + 8) * SBS + ks * 8 + tg;
                        af[mt][0] = rtf(p0[0]);
                        af[mt][1] = rtf(p1[0]);
                        af[mt][2] = rtf(p0[4]);
                        af[mt][3] = rtf(p1[4]);
                    }
                    #pragma unroll
                    for (int nt = 0; nt < 8; nt++) {
                        const float* pb = bB + (nb + nt * 8 + g) * SBS + ks * 8 + tg;
                        unsigned b0 = rtf(pb[0]);
                        unsigned b1 = rtf(pb[4]);
                        mma8(acc[0][nt], af[0][0], af[0][1], af[0][2], af[0][3], b0, b1);
                        mma8(acc[1][nt], af[1][0], af[1][1], af[1][2], af[1][3], b0, b1);
                    }
                }
                __syncthreads();
            }

            #pragma unroll
            for (int mt = 0; mt < 2; mt++) {
                #pragma unroll
                for (int nt = 0; nt < 8; nt++) {
                    const int col = hbase + nb + nt * 8 + 2 * tg;
                    const int r0 = mt * 16 + g;
                    const int r1 = r0 + 8;
                    if (m0 + r0 < cnt) {
                        float2 v = make_float2(acc[mt][nt][0], acc[mt][nt][1]);
                        *(float2*)(g_part + (size_t)(off + m0 + r0) * HID + col) = v;
                    }
                    if (m0 + r1 < cnt) {
                        float2 v = make_float2(acc[mt][nt][2], acc[mt][nt][3]);
                        *(float2*)(g_part + (size_t)(off + m0 + r1) * HID + col) = v;
                    }
                }
            }
            __syncthreads();
        }

        __syncthreads();
        if (tid == 0) {
            __threadfence();
            atomicAdd(&g_s2cnt[e], 1);
        }
        return;
    }

    // =========================== COMBINE ===========================
    {
        const int t = bid - (S1_BLOCKS + S2_BLOCKS);
        // wait only on this token's 8 experts (they finish long before expert 63)
        if (tid == 0) {
            #pragma unroll
            for (int s = 0; s < TOPK; s++) {
                int es = g_exp[t * TOPK + s];
                spin_until(&g_s2cnt[es], 8);
            }
            __threadfence();
        }
        __syncthreads();

        int   gi[TOPK];
        float gw[TOPK];
        #pragma unroll
        for (int s = 0; s < TOPK; s++) {
            gi[s] = g_map[t * TOPK + s];
            gw[s] = g_gate[t * TOPK + s];
        }
        #pragma unroll
        for (int j = 0; j < 4; j++) {
            const int c4 = tid + j * THR;
            float4 acc = make_float4(0.f, 0.f, 0.f, 0.f);
            #pragma unroll
            for (int s = 0; s < TOPK; s++) {
                const float4 v = *(const float4*)(g_part + (size_t)gi[s] * HID + 4 * c4);
                const float w = gw[s];
                acc.x += w * v.x; acc.y += w * v.y;
                acc.z += w * v.z; acc.w += w * v.w;
            }
            *(float4*)(out + (size_t)t * HID + 4 * c4) = acc;
        }
    }
}

// =====================================================================
extern "C" void kernel_launch(void* const* d_in, const int* in_sizes, int n_in,
                              void* d_out, int out_size) {
    (void)in_sizes; (void)n_in; (void)out_size;
    const float* x      = (const float*)d_in[0];
    const float* logits = (const float*)d_in[1];
    const float* w1     = (const float*)d_in[2];
    const float* w2     = (const float*)d_in[3];
    float* out          = (float*)d_out;

    static int configured = 0;
    if (!configured) {
        cudaFuncSetAttribute(moe_kernel,
                             cudaFuncAttributeMaxDynamicSharedMemorySize, SMEM_BYTES);
        configured = 1;
    }

    routing_kernel<<<1, T_TOK>>>(logits);
    moe_kernel<<<TOTAL_BLOCKS, THR, SMEM_BYTES>>>(x, w1, w2, out);
}

// round 14
// speedup vs baseline: 1.1512x; 1.0370x over previous
#include <cuda_runtime.h>
#include <cstdint>
#include <math.h>

#define T_TOK 128
#define HID   2048
#define NEXP  64
#define I2    2816
#define INTER 1408
#define TOPK  8
#define NASSIGN 1024

#define KC   32
#define MT   32
#define SBS  36
#define THR  128

#define S1_BLOCKS (NEXP * 11)          // 704 : (e, ib) ib<11, 128 pairs each
#define S2_BLOCKS (NEXP * 8)           // 512 : (e, hb) hb<8, 256 h-rows each
#define CMB_BLOCKS T_TOK               // 128
#define TOTAL_BLOCKS (S1_BLOCKS + S2_BLOCKS + CMB_BLOCKS)   // 1344

#define BUF_FLOATS (256 * SBS + MT * SBS)
#define BUF_BYTES  (BUF_FLOATS * 4)
#define SMEM_BYTES (2 * BUF_BYTES)     // 82944

// ---- scratch ----
__device__ float g_act[NASSIGN * INTER];
__device__ float g_part[NASSIGN * HID];
__device__ float g_gate[NASSIGN];
__device__ int   g_map[NASSIGN];
__device__ int   g_exp[NASSIGN];       // (t,slot) -> expert id
__device__ int   g_tok[NASSIGN];
__device__ int   g_off[NEXP + 1];
__device__ int   g_s1done[NEXP];
__device__ int   g_s2cnt[NEXP];

// =====================================================================
// helpers
// =====================================================================
__device__ __forceinline__ unsigned su32(const void* p) {
    return (unsigned)__cvta_generic_to_shared(p);
}
__device__ __forceinline__ void cp16(unsigned dst, const void* src, int bytes) {
    asm volatile("cp.async.cg.shared.global [%0], [%1], 16, %2;\n"
                 :: "r"(dst), "l"(src), "r"(bytes));
}
__device__ __forceinline__ void cp_commit() { asm volatile("cp.async.commit_group;\n"); }
__device__ __forceinline__ void cp_wait1()  { asm volatile("cp.async.wait_group 1;\n"); }
__device__ __forceinline__ void cp_wait0()  { asm volatile("cp.async.wait_group 0;\n"); }

__device__ __forceinline__ unsigned rtf(float f) {   // f32 -> tf32 round-to-nearest
    return __float_as_uint(f) + 0x1000u;
}
__device__ __forceinline__ void mma8(float* d,
                                     unsigned a0, unsigned a1, unsigned a2, unsigned a3,
                                     unsigned b0, unsigned b1) {
    asm volatile(
        "mma.sync.aligned.m16n8k8.row.col.f32.tf32.tf32.f32 "
        "{%0,%1,%2,%3}, {%4,%5,%6,%7}, {%8,%9}, {%0,%1,%2,%3};\n"
        : "+f"(d[0]), "+f"(d[1]), "+f"(d[2]), "+f"(d[3])
        : "r"(a0), "r"(a1), "r"(a2), "r"(a3), "r"(b0), "r"(b1));
}

__device__ __forceinline__ void spin_until(volatile int* p, int need) {
    while (*p < need) __nanosleep(64);
}

// =====================================================================
// Routing: top-8 per token; vectorized float4 logits load (single pass),
// count/scatter via shared-memory atomics. Output bit-identical
// regardless of scatter order (GEMMs and fixed-slot combine are
// order-invariant).
// =====================================================================
__global__ void routing_kernel(const float* __restrict__ logits) {
    __shared__ float sp[T_TOK][NEXP + 1];
    __shared__ int scnt[NEXP];
    __shared__ int soff[NEXP + 1];
    __shared__ int scur[NEXP];

    const int t = threadIdx.x;   // 128 threads, one token each

    if (t < NEXP) { g_s1done[t] = 0; g_s2cnt[t] = 0; scnt[t] = 0; scur[t] = 0; }
    __syncthreads();

    // single-pass vectorized load: 16 float4 = 64 logits into registers
    float4 lv[16];
    const float4* lrow = (const float4*)(logits + t * NEXP);
    #pragma unroll
    for (int i = 0; i < 16; i++) lv[i] = lrow[i];

    float mx = -1e30f;
    #pragma unroll
    for (int i = 0; i < 16; i++) {
        mx = fmaxf(mx, fmaxf(fmaxf(lv[i].x, lv[i].y), fmaxf(lv[i].z, lv[i].w)));
    }
    #pragma unroll
    for (int i = 0; i < 16; i++) {
        sp[t][4 * i + 0] = expf(lv[i].x - mx);
        sp[t][4 * i + 1] = expf(lv[i].y - mx);
        sp[t][4 * i + 2] = expf(lv[i].z - mx);
        sp[t][4 * i + 3] = expf(lv[i].w - mx);
    }

    float wsel[TOPK]; int isel[TOPK];
    for (int s = 0; s < TOPK; s++) {
        float best = -1.f; int bj = 0;
        for (int e = 0; e < NEXP; e++) {
            float v = sp[t][e];
            if (v > best) { best = v; bj = e; }
        }
        wsel[s] = best; isel[s] = bj; sp[t][bj] = -2.f;
    }
    float gs = 0.f;
    #pragma unroll
    for (int s = 0; s < TOPK; s++) gs += wsel[s];
    float inv = 1.f / gs;
    #pragma unroll
    for (int s = 0; s < TOPK; s++) {
        g_gate[t * TOPK + s] = wsel[s] * inv;
        g_exp[t * TOPK + s]  = isel[s];
        atomicAdd(&scnt[isel[s]], 1);
    }
    __syncthreads();

    if (t == 0) {
        int acc = 0;
        for (int e = 0; e < NEXP; e++) { soff[e] = acc; acc += scnt[e]; }
        soff[NEXP] = acc;
        for (int e = 0; e <= NEXP; e++) g_off[e] = soff[e];
    }
    __syncthreads();

    #pragma unroll
    for (int s = 0; s < TOPK; s++) {
        int e = isel[s];
        int pos = soff[e] + atomicAdd(&scur[e], 1);
        g_tok[pos] = t;
        g_map[t * TOPK + s] = pos;
    }
}

// =====================================================================
// Fused MoE kernel (exact R12-record stream; byte-frozen):
// bids [0,704) stage1, [704,1216) stage2, [1216,1344) combine
// =====================================================================
__global__ void __launch_bounds__(THR)
moe_kernel(const float* __restrict__ x, const float* __restrict__ w1,
           const float* __restrict__ w2, float* __restrict__ out) {
    extern __shared__ __align__(16) float dynsm[];
    const unsigned smb = su32(dynsm);

    const int bid = blockIdx.x;
    const int tid = threadIdx.x;
    const int wid = tid >> 5, lane = tid & 31;
    const int g   = lane >> 2, tg = lane & 3;
    const int nb  = wid * 64;

    // =========================== STAGE 1 ===========================
    if (bid < S1_BLOCKS) {
        const int e  = bid / 11;
        const int ib = bid % 11;
        const int off = g_off[e];
        const int cnt = g_off[e + 1] - off;
        const int ibase = ib * 128;
        const int ngrp = (cnt + MT - 1) / MT;
        const float* w1e = w1 + (size_t)e * I2 * HID;

        __shared__ int toks[MT];

        const float* bsrc[16];
        unsigned     bdst[16];
        #pragma unroll
        for (int j = 0; j < 16; j++) {
            int idx = j * THR + tid;
            int c = idx >> 3, k4 = idx & 7;
            int p = c >> 1;
            int gr = (c & 1) ? (INTER + ibase + p) : (ibase + p);
            bsrc[j] = w1e + (size_t)gr * HID + k4 * 4;
            bdst[j] = (unsigned)(c * SBS + k4 * 4) * 4u;
        }

        for (int grp = 0; grp < ngrp; grp++) {
            const int m0 = grp * MT;
            if (tid < MT) toks[tid] = (m0 + tid < cnt) ? g_tok[off + m0 + tid] : -1;
            __syncthreads();

            const float* asrc[2];
            int aval[2];
            unsigned adst[2];
            #pragma unroll
            for (int j = 0; j < 2; j++) {
                int idx = j * THR + tid;
                int m = idx >> 3, k4 = idx & 7;
                int tok = toks[m];
                asrc[j] = x + (size_t)(tok < 0 ? 0 : tok) * HID + k4 * 4;
                aval[j] = (tok >= 0) ? 16 : 0;
                adst[j] = (unsigned)((256 * SBS) + m * SBS + k4 * 4) * 4u;
            }

            float acc[2][8][4];
            #pragma unroll
            for (int a = 0; a < 2; a++)
                #pragma unroll
                for (int b = 0; b < 8; b++)
                    #pragma unroll
                    for (int cix = 0; cix < 4; cix++) acc[a][b][cix] = 0.f;

            const int NK = HID / KC;   // 64
            #pragma unroll
            for (int j = 0; j < 16; j++) cp16(smb + bdst[j], bsrc[j], 16);
            #pragma unroll
            for (int j = 0; j < 2; j++)  cp16(smb + adst[j], asrc[j], aval[j]);
            cp_commit();

            for (int kc = 0; kc < NK; kc++) {
                const int par = kc & 1;
                if (kc + 1 < NK) {
                    const unsigned boff = (par ^ 1) ? (unsigned)BUF_BYTES : 0u;
                    const int ko = (kc + 1) * KC;
                    #pragma unroll
                    for (int j = 0; j < 16; j++) cp16(smb + boff + bdst[j], bsrc[j] + ko, 16);
                    #pragma unroll
                    for (int j = 0; j < 2; j++)  cp16(smb + boff + adst[j], asrc[j] + ko, aval[j]);
                    cp_commit();
                    cp_wait1();
                } else {
                    cp_wait0();
                }
                __syncthreads();

                const float* bB = dynsm + par * BUF_FLOATS;
                const float* bA = bB + 256 * SBS;

                #pragma unroll
                for (int ks = 0; ks < 4; ks++) {
                    unsigned af[2][4];
                    #pragma unroll
                    for (int mt = 0; mt < 2; mt++) {
                        const int r = mt * 16 + g;
                        const float* p0 = bA + r * SBS + ks * 8 + tg;
                        const float* p1 = bA + (r + 8) * SBS + ks * 8 + tg;
                        af[mt][0] = rtf(p0[0]);
                        af[mt][1] = rtf(p1[0]);
                        af[mt][2] = rtf(p0[4]);
                        af[mt][3] = rtf(p1[4]);
                    }
                    #pragma unroll
                    for (int nt = 0; nt < 8; nt++) {
                        const float* pb = bB + (nb + nt * 8 + g) * SBS + ks * 8 + tg;
                        unsigned b0 = rtf(pb[0]);
                        unsigned b1 = rtf(pb[4]);
                        mma8(acc[0][nt], af[0][0], af[0][1], af[0][2], af[0][3], b0, b1);
                        mma8(acc[1][nt], af[1][0], af[1][1], af[1][2], af[1][3], b0, b1);
                    }
                }
                __syncthreads();
            }

            // epilogue: silu(up)*gate, pair interleave keeps both in-thread
            #pragma unroll
            for (int mt = 0; mt < 2; mt++) {
                #pragma unroll
                for (int nt = 0; nt < 8; nt++) {
                    const int pl = ibase + nb / 2 + nt * 4 + tg;
                    const int r0 = mt * 16 + g;
                    const int r1 = r0 + 8;
                    if (m0 + r0 < cnt) {
                        float u = acc[mt][nt][0];
                        g_act[(size_t)(off + m0 + r0) * INTER + pl] =
                            u / (1.f + expf(-u)) * acc[mt][nt][1];
                    }
                    if (m0 + r1 < cnt) {
                        float u = acc[mt][nt][2];
                        g_act[(size_t)(off + m0 + r1) * INTER + pl] =
                            u / (1.f + expf(-u)) * acc[mt][nt][3];
                    }
                }
            }
            __syncthreads();
        }

        __syncthreads();
        if (tid == 0) {
            __threadfence();
            atomicAdd(&g_s1done[e], 1);
        }
        return;
    }

    // =========================== STAGE 2 ===========================
    if (bid < S1_BLOCKS + S2_BLOCKS) {
        const int sb = bid - S1_BLOCKS;
        const int e  = sb / 8;
        const int hb = sb % 8;
        const int off = g_off[e];
        const int cnt = g_off[e + 1] - off;
        const int hbase = hb * 256;
        const int ngrp = (cnt + MT - 1) / MT;
        const float* w2e = w2 + (size_t)e * HID * INTER;

        if (tid == 0) {
            spin_until(&g_s1done[e], 11);
            __threadfence();
        }
        __syncthreads();

        const float* bsrc[16];
        unsigned     bdst[16];
        #pragma unroll
        for (int j = 0; j < 16; j++) {
            int idx = j * THR + tid;
            int c = idx >> 3, k4 = idx & 7;
            bsrc[j] = w2e + (size_t)(hbase + c) * INTER + k4 * 4;
            bdst[j] = (unsigned)(c * SBS + k4 * 4) * 4u;
        }

        for (int grp = 0; grp < ngrp; grp++) {
            const int m0 = grp * MT;

            const float* asrc[2];
            int aval[2];
            unsigned adst[2];
            #pragma unroll
            for (int j = 0; j < 2; j++) {
                int idx = j * THR + tid;
                int m = idx >> 3, k4 = idx & 7;
                int valid = (m0 + m) < cnt;
                asrc[j] = g_act + (size_t)(off + (valid ? m0 + m : 0)) * INTER + k4 * 4;
                aval[j] = valid ? 16 : 0;
                adst[j] = (unsigned)((256 * SBS) + m * SBS + k4 * 4) * 4u;
            }

            float acc[2][8][4];
            #pragma unroll
            for (int a = 0; a < 2; a++)
                #pragma unroll
                for (int b = 0; b < 8; b++)
                    #pragma unroll
                    for (int cix = 0; cix < 4; cix++) acc[a][b][cix] = 0.f;

            const int NK = INTER / KC;   // 44
            #pragma unroll
            for (int j = 0; j < 16; j++) cp16(smb + bdst[j], bsrc[j], 16);
            #pragma unroll
            for (int j = 0; j < 2; j++)  cp16(smb + adst[j], asrc[j], aval[j]);
            cp_commit();

            for (int kc = 0; kc < NK; kc++) {
                const int par = kc & 1;
                if (kc + 1 < NK) {
                    const unsigned boff = (par ^ 1) ? (unsigned)BUF_BYTES : 0u;
                    const int ko = (kc + 1) * KC;
                    #pragma unroll
                    for (int j = 0; j < 16; j++) cp16(smb + boff + bdst[j], bsrc[j] + ko, 16);
                    #pragma unroll
                    for (int j = 0; j < 2; j++)  cp16(smb + boff + adst[j], asrc[j] + ko, aval[j]);
                    cp_commit();
                    cp_wait1();
                } else {
                    cp_wait0();
                }
                __syncthreads();

                const float* bB = dynsm + par * BUF_FLOATS;
                const float* bA = bB + 256 * SBS;

                #pragma unroll
                for (int ks = 0; ks < 4; ks++) {
                    unsigned af[2][4];
                    #pragma unroll
                    for (int mt = 0; mt < 2; mt++) {
                        const int r = mt * 16 + g;
                        const float* p0 = bA + r * SBS + ks * 8 + tg;
                        const float* p1 = bA + (r + 8) * SBS + ks * 8 + tg;
                        af[mt][0] = rtf(p0[0]);
                        af[mt][1] = rtf(p1[0]);
                        af[mt][2] = rtf(p0[4]);
                        af[mt][3] = rtf(p1[4]);
                    }
                    #pragma unroll
                    for (int nt = 0; nt < 8; nt++) {
                        const float* pb = bB + (nb + nt * 8 + g) * SBS + ks * 8 + tg;
                        unsigned b0 = rtf(pb[0]);
                        unsigned b1 = rtf(pb[4]);
                        mma8(acc[0][nt], af[0][0], af[0][1], af[0][2], af[0][3], b0, b1);
                        mma8(acc[1][nt], af[1][0], af[1][1], af[1][2], af[1][3], b0, b1);
                    }
                }
                __syncthreads();
            }

            #pragma unroll
            for (int mt = 0; mt < 2; mt++) {
                #pragma unroll
                for (int nt = 0; nt < 8; nt++) {
                    const int col = hbase + nb + nt * 8 + 2 * tg;
                    const int r0 = mt * 16 + g;
                    const int r1 = r0 + 8;
                    if (m0 + r0 < cnt) {
                        float2 v = make_float2(acc[mt][nt][0], acc[mt][nt][1]);
                        *(float2*)(g_part + (size_t)(off + m0 + r0) * HID + col) = v;
                    }
                    if (m0 + r1 < cnt) {
                        float2 v = make_float2(acc[mt][nt][2], acc[mt][nt][3]);
                        *(float2*)(g_part + (size_t)(off + m0 + r1) * HID + col) = v;
                    }
                }
            }
            __syncthreads();
        }

        __syncthreads();
        if (tid == 0) {
            __threadfence();
            atomicAdd(&g_s2cnt[e], 1);
        }
        return;
    }

    // =========================== COMBINE ===========================
    {
        const int t = bid - (S1_BLOCKS + S2_BLOCKS);
        // wait only on this token's 8 experts (they finish long before expert 63)
        if (tid == 0) {
            #pragma unroll
            for (int s = 0; s < TOPK; s++) {
                int es = g_exp[t * TOPK + s];
                spin_until(&g_s2cnt[es], 8);
            }
            __threadfence();
        }
        __syncthreads();

        int   gi[TOPK];
        float gw[TOPK];
        #pragma unroll
        for (int s = 0; s < TOPK; s++) {
            gi[s] = g_map[t * TOPK + s];
            gw[s] = g_gate[t * TOPK + s];
        }
        #pragma unroll
        for (int j = 0; j < 4; j++) {
            const int c4 = tid + j * THR;
            float4 acc = make_float4(0.f, 0.f, 0.f, 0.f);
            #pragma unroll
            for (int s = 0; s < TOPK; s++) {
                const float4 v = *(const float4*)(g_part + (size_t)gi[s] * HID + 4 * c4);
                const float w = gw[s];
                acc.x += w * v.x; acc.y += w * v.y;
                acc.z += w * v.z; acc.w += w * v.w;
            }
            *(float4*)(out + (size_t)t * HID + 4 * c4) = acc;
        }
    }
}

// =====================================================================
extern "C" void kernel_launch(void* const* d_in, const int* in_sizes, int n_in,
                              void* d_out, int out_size) {
    (void)in_sizes; (void)n_in; (void)out_size;
    const float* x      = (const float*)d_in[0];
    const float* logits = (const float*)d_in[1];
    const float* w1     = (const float*)d_in[2];
    const float* w2     = (const float*)d_in[3];
    float* out          = (float*)d_out;

    static int configured = 0;
    if (!configured) {
        cudaFuncSetAttribute(moe_kernel,
                             cudaFuncAttributeMaxDynamicSharedMemorySize, SMEM_BYTES);
        configured = 1;
    }

    routing_kernel<<<1, T_TOK>>>(logits);
    moe_kernel<<<TOTAL_BLOCKS, THR, SMEM_BYTES>>>(x, w1, w2, out);
}